// round 13
// baseline (speedup 1.0000x reference)
#include <cuda_runtime.h>
#include <cuda_fp16.h>
#include <math.h>
#include <stdint.h>

#define BB 64
#define TT 2048
#define DD 512
#define UU 512

// ---------------- device scratch ----------------
__device__ float g_comb[BB * UU];
__device__ float g_spart[2 * BB * TT];
// A fragments: [b][t16 0..127][k16 0..31][lane 0..31] -> uint4 (a0,a1,a2,a3) fp16x2
__device__ uint4 g_afrag[BB * 128 * 32 * 32];
// B fragments (fp16, 2 n8 per uint4): [n4 0..31][k16 0..31][lane 0..31]
__device__ uint4 g_bfrag[32 * 32 * 32];

// ---------------- helpers ----------------
__device__ __forceinline__ uint32_t pack_h2(float x, float y) {
    __half2 h = __floats2half2_rn(x, y);
    return *(uint32_t*)&h;
}

__device__ __forceinline__ float tanh_fast(float x) {
    float y;
    asm("tanh.approx.f32 %0, %1;" : "=f"(y) : "f"(x));
    return y;
}

// L1-bypassing load (keep B out of L1 so A stays resident)
__device__ __forceinline__ uint4 ldg_cg(const uint4* p) {
    uint4 v;
    asm volatile("ld.global.cg.v4.u32 {%0,%1,%2,%3}, [%4];"
                 : "=r"(v.x), "=r"(v.y), "=r"(v.z), "=r"(v.w) : "l"(p));
    return v;
}

__device__ __forceinline__ void mma_f16(float* d, const uint4& a, uint32_t b0, uint32_t b1) {
    asm volatile(
        "mma.sync.aligned.m16n8k16.row.col.f32.f16.f16.f32 "
        "{%0,%1,%2,%3}, {%4,%5,%6,%7}, {%8,%9}, {%0,%1,%2,%3};"
        : "+f"(d[0]), "+f"(d[1]), "+f"(d[2]), "+f"(d[3])
        : "r"(a.x), "r"(a.y), "r"(a.z), "r"(a.w), "r"(b0), "r"(b1));
}

// ---------------- prep: features fp32 -> fp16 fragment-major ----------------
__global__ void prep_afrag_kernel(const float* __restrict__ feat) {
    int gidx = blockIdx.x * 256 + threadIdx.x;      // 8388608
    int lane = gidx & 31;
    int k16 = (gidx >> 5) & 31;
    int t16 = (gidx >> 10) & 127;
    int b = gidx >> 17;
    int g = lane >> 2, tg = lane & 3;
    int tA = t16 * 16 + g;
    int kA = k16 * 16 + 2 * tg;
    const float* base = feat + ((size_t)b * TT) * DD;
    float2 f00 = *(const float2*)(base + (size_t)tA * DD + kA);
    float2 f10 = *(const float2*)(base + (size_t)(tA + 8) * DD + kA);
    float2 f01 = *(const float2*)(base + (size_t)tA * DD + kA + 8);
    float2 f11 = *(const float2*)(base + (size_t)(tA + 8) * DD + kA + 8);
    uint4 o;
    o.x = pack_h2(f00.x, f00.y);
    o.y = pack_h2(f10.x, f10.y);
    o.z = pack_h2(f01.x, f01.y);
    o.w = pack_h2(f11.x, f11.y);
    g_afrag[gidx] = o;
}

// ---------------- prep: W1 -> fp16 fragment-major (2 n8 per uint4) ----------------
__global__ void prep_bfrag_kernel(const float* __restrict__ W1) {
    int gidx = blockIdx.x * 256 + threadIdx.x;      // 32768
    int lane = gidx & 31;
    int k16 = (gidx >> 5) & 31;
    int n4 = gidx >> 10;
    int g = lane >> 2, tg = lane & 3;
    int k = k16 * 16 + 2 * tg;
    int ua = (2 * n4) * 8 + g;
    int ub = (2 * n4 + 1) * 8 + g;
    uint4 o;
    o.x = pack_h2(W1[(size_t)k * UU + ua],       W1[(size_t)(k + 1) * UU + ua]);
    o.y = pack_h2(W1[(size_t)(k + 8) * UU + ua], W1[(size_t)(k + 9) * UU + ua]);
    o.z = pack_h2(W1[(size_t)k * UU + ub],       W1[(size_t)(k + 1) * UU + ub]);
    o.w = pack_h2(W1[(size_t)(k + 8) * UU + ub], W1[(size_t)(k + 9) * UU + ub]);
    g_bfrag[gidx] = o;
}

// ---------------- comb[b][u] ----------------
__global__ void comb_kernel(const float* __restrict__ hidden,
                            const float* __restrict__ W2,
                            const float* __restrict__ W1b,
                            const float* __restrict__ W2b) {
    int b = blockIdx.x;
    int u = threadIdx.x;
    __shared__ float h[DD];
    h[u] = hidden[b * DD + u];
    __syncthreads();
    float acc = W1b[u] + W2b[u];
#pragma unroll 8
    for (int d = 0; d < DD; ++d)
        acc = fmaf(h[d], W2[d * UU + u], acc);
    g_comb[b * UU + u] = acc;
}

// ---------------- score GEMM: both nchunks per CTA, A L1-resident, B via .cg ----------------
// grid (16 ttile, 64 b), 512 threads = 16 warps (4 warpM x 4 warpN)
__global__ void __launch_bounds__(512)
score_kernel(const float* __restrict__ Vw) {
    __shared__ float comb_s[512];
    __shared__ float v_s[512];
    __shared__ float srow[128];

    int tid = threadIdx.x;
    int wid = tid >> 5, lane = tid & 31;
    int warpM = wid & 3, warpN = wid >> 2;
    int g = lane >> 2, tg = lane & 3;

    int t0 = blockIdx.x << 7;
    int b = blockIdx.y;

    comb_s[tid] = g_comb[b * UU + tid];
    v_s[tid] = Vw[tid];

    int tt0 = (t0 >> 4) + warpM * 2;
    const uint4* pA0 = g_afrag + (((size_t)(b * 128 + tt0) * 32) * 32 + lane);
    const uint4* pA1 = pA0 + 32 * 32;

#pragma unroll 1
    for (int nch = 0; nch < 2; ++nch) {
        const uint4* pB = g_bfrag + (((size_t)(nch * 16 + warpN * 4) * 32) * 32 + lane);

        if (tid < 128) srow[tid] = 0.f;

        float acc[2][8][4];
#pragma unroll
        for (int i = 0; i < 2; ++i)
#pragma unroll
            for (int j = 0; j < 8; ++j)
#pragma unroll
                for (int q = 0; q < 4; ++q) acc[i][j][q] = 0.f;

        uint4 Ab[2][2], Bb[2][4];
        Ab[0][0] = pA0[0];
        Ab[0][1] = pA1[0];
#pragma unroll
        for (int j = 0; j < 4; ++j) Bb[0][j] = ldg_cg(pB + j * 1024);

#pragma unroll 2
        for (int k16 = 0; k16 < 32; ++k16) {
            int cur = k16 & 1, nxt = cur ^ 1;
            if (k16 < 31) {
                int off = (k16 + 1) * 32;
                Ab[nxt][0] = pA0[off];
                Ab[nxt][1] = pA1[off];
#pragma unroll
                for (int j = 0; j < 4; ++j) Bb[nxt][j] = ldg_cg(pB + j * 1024 + off);
            }
#pragma unroll
            for (int n4 = 0; n4 < 4; ++n4) {
                uint4 B4 = Bb[cur][n4];
                mma_f16(acc[0][2 * n4],     Ab[cur][0], B4.x, B4.y);
                mma_f16(acc[0][2 * n4 + 1], Ab[cur][0], B4.z, B4.w);
                mma_f16(acc[1][2 * n4],     Ab[cur][1], B4.x, B4.y);
                mma_f16(acc[1][2 * n4 + 1], Ab[cur][1], B4.z, B4.w);
            }
        }

        __syncthreads();

        float s[4] = {0.f, 0.f, 0.f, 0.f};
#pragma unroll
        for (int nt = 0; nt < 8; ++nt) {
#pragma unroll
            for (int j = 0; j < 2; ++j) {
                int ul = nch * 256 + warpN * 64 + nt * 8 + 2 * tg + j;
                float cb = comb_s[ul], vv = v_s[ul];
                s[0] = fmaf(vv, tanh_fast(acc[0][nt][j] + cb), s[0]);
                s[1] = fmaf(vv, tanh_fast(acc[0][nt][2 + j] + cb), s[1]);
                s[2] = fmaf(vv, tanh_fast(acc[1][nt][j] + cb), s[2]);
                s[3] = fmaf(vv, tanh_fast(acc[1][nt][2 + j] + cb), s[3]);
            }
        }
#pragma unroll
        for (int i = 0; i < 4; ++i) {
            s[i] += __shfl_xor_sync(0xffffffffu, s[i], 1);
            s[i] += __shfl_xor_sync(0xffffffffu, s[i], 2);
        }
        if (tg == 0) {
            int rbase = warpM * 32;
            atomicAdd(&srow[rbase + g], s[0]);
            atomicAdd(&srow[rbase + g + 8], s[1]);
            atomicAdd(&srow[rbase + 16 + g], s[2]);
            atomicAdd(&srow[rbase + 16 + g + 8], s[3]);
        }
        __syncthreads();
        if (tid < 128)
            g_spart[(size_t)nch * BB * TT + b * TT + t0 + tid] = srow[tid];
    }
}

// ---------------- context: inline softmax stats + fp16-fragment reduction ----------------
// grid (64 b, 4 kgroup), 256 threads = 8 warps; warp w -> k16 = kgroup*8 + w
__global__ void __launch_bounds__(256)
ctx_kernel(float* __restrict__ out) {
    int b = blockIdx.x;
    int kg = blockIdx.y;
    int tid = threadIdx.x;
    int wid = tid >> 5, lane = tid & 31;
    int g = lane >> 2, tg = lane & 3;
    int k16 = kg * 8 + wid;

    __shared__ float w[TT];
    __shared__ float red[256];

    float m = -INFINITY;
    for (int t = tid; t < TT; t += 256) {
        float sc = g_spart[b * TT + t] + g_spart[BB * TT + b * TT + t];
        w[t] = sc;
        m = fmaxf(m, sc);
    }
    red[tid] = m;
    __syncthreads();
    for (int s = 128; s > 0; s >>= 1) {
        if (tid < s) red[tid] = fmaxf(red[tid], red[tid + s]);
        __syncthreads();
    }
    float mx = red[0];
    __syncthreads();
    float sm = 0.f;
    for (int t = tid; t < TT; t += 256)
        sm += expf(w[t] - mx);
    red[tid] = sm;
    __syncthreads();
    for (int s = 128; s > 0; s >>= 1) {
        if (tid < s) red[tid] += red[tid + s];
        __syncthreads();
    }
    float inv = 1.0f / red[0];
    __syncthreads();
    for (int t = tid; t < TT; t += 256)
        w[t] = expf(w[t] - mx) * inv;
    __syncthreads();

    const uint4* pA = g_afrag + (((size_t)(b * 128) * 32 + k16) * 32 + lane);
    float a0 = 0.f, a1 = 0.f, a2 = 0.f, a3 = 0.f;
#pragma unroll 4
    for (int t16 = 0; t16 < 128; ++t16) {
        uint4 v = pA[(size_t)t16 * 1024];
        float wlo = w[t16 * 16 + g];
        float whi = w[t16 * 16 + 8 + g];
        float2 f;
        f = __half22float2(*(__half2*)&v.x);
        a0 = fmaf(wlo, f.x, a0); a1 = fmaf(wlo, f.y, a1);
        f = __half22float2(*(__half2*)&v.y);
        a0 = fmaf(whi, f.x, a0); a1 = fmaf(whi, f.y, a1);
        f = __half22float2(*(__half2*)&v.z);
        a2 = fmaf(wlo, f.x, a2); a3 = fmaf(wlo, f.y, a3);
        f = __half22float2(*(__half2*)&v.w);
        a2 = fmaf(whi, f.x, a2); a3 = fmaf(whi, f.y, a3);
    }
#pragma unroll
    for (int o = 4; o <= 16; o <<= 1) {
        a0 += __shfl_xor_sync(0xffffffffu, a0, o);
        a1 += __shfl_xor_sync(0xffffffffu, a1, o);
        a2 += __shfl_xor_sync(0xffffffffu, a2, o);
        a3 += __shfl_xor_sync(0xffffffffu, a3, o);
    }
    if (g == 0) {
        int d = k16 * 16 + 2 * tg;
        out[b * DD + d]     = a0;
        out[b * DD + d + 1] = a1;
        out[b * DD + d + 8] = a2;
        out[b * DD + d + 9] = a3;
    }
}

// ---------------- launch ----------------
extern "C" void kernel_launch(void* const* d_in, const int* in_sizes, int n_in,
                              void* d_out, int out_size) {
    const float* features = (const float*)d_in[0];
    const float* hidden   = (const float*)d_in[1];
    const float* W1_w     = (const float*)d_in[2];
    const float* W1_b     = (const float*)d_in[3];
    const float* W2_w     = (const float*)d_in[4];
    const float* W2_b     = (const float*)d_in[5];
    const float* V_w      = (const float*)d_in[6];
    // V_b: constant shift, softmax-invariant -> dropped
    float* out = (float*)d_out;

    prep_afrag_kernel<<<BB * 128 * 32 * 32 / 256, 256>>>(features);
    prep_bfrag_kernel<<<32 * 32 * 32 / 256, 256>>>(W1_w);
    comb_kernel<<<BB, UU>>>(hidden, W2_w, W1_b, W2_b);

    dim3 sgrid(16, BB);
    score_kernel<<<sgrid, 512>>>(V_w);

    dim3 cgrid(BB, 4);
    ctx_kernel<<<cgrid, 256>>>(out);
}

// round 14
// speedup vs baseline: 1.2973x; 1.2973x over previous
#include <cuda_runtime.h>
#include <cuda_fp16.h>
#include <math.h>
#include <stdint.h>

#define BB 64
#define TT 2048
#define DD 512
#define UU 512

// ---------------- device scratch ----------------
__device__ float g_comb[BB * UU];
__device__ float g_spart[2 * BB * TT];
// A fragments: [b][t16 0..127][k16 0..31][lane 0..31] -> uint4 (a0,a1,a2,a3) fp16x2
__device__ uint4 g_afrag[BB * 128 * 32 * 32];
// B fragments (fp16, 2 n8 per uint4): [n4 0..31][k16 0..31][lane 0..31]
__device__ uint4 g_bfrag[32 * 32 * 32];

// ---------------- helpers ----------------
__device__ __forceinline__ uint32_t smem_u32(const void* p) {
    uint32_t a;
    asm("{ .reg .u64 t; cvta.to.shared.u64 t, %1; cvt.u32.u64 %0, t; }" : "=r"(a) : "l"(p));
    return a;
}
__device__ __forceinline__ void cpa16(uint32_t dst, const void* src) {
    asm volatile("cp.async.cg.shared.global [%0], [%1], 16;" :: "r"(dst), "l"(src) : "memory");
}
#define CP_COMMIT() asm volatile("cp.async.commit_group;" ::: "memory")
#define CP_WAIT(n)  asm volatile("cp.async.wait_group %0;" :: "n"(n) : "memory")

__device__ __forceinline__ uint32_t pack_h2(float x, float y) {
    __half2 h = __floats2half2_rn(x, y);
    return *(uint32_t*)&h;
}

__device__ __forceinline__ float tanh_fast(float x) {
    float y;
    asm("tanh.approx.f32 %0, %1;" : "=f"(y) : "f"(x));
    return y;
}

__device__ __forceinline__ void mma_f16(float* d, const uint4& a, uint32_t b0, uint32_t b1) {
    asm volatile(
        "mma.sync.aligned.m16n8k16.row.col.f32.f16.f16.f32 "
        "{%0,%1,%2,%3}, {%4,%5,%6,%7}, {%8,%9}, {%0,%1,%2,%3};"
        : "+f"(d[0]), "+f"(d[1]), "+f"(d[2]), "+f"(d[3])
        : "r"(a.x), "r"(a.y), "r"(a.z), "r"(a.w), "r"(b0), "r"(b1));
}

// ---------------- prep: features fp32 -> fp16 fragment-major ----------------
__global__ void prep_afrag_kernel(const float* __restrict__ feat) {
    int gidx = blockIdx.x * 256 + threadIdx.x;      // 8388608
    int lane = gidx & 31;
    int k16 = (gidx >> 5) & 31;
    int t16 = (gidx >> 10) & 127;
    int b = gidx >> 17;
    int g = lane >> 2, tg = lane & 3;
    int tA = t16 * 16 + g;
    int kA = k16 * 16 + 2 * tg;
    const float* base = feat + ((size_t)b * TT) * DD;
    float2 f00 = *(const float2*)(base + (size_t)tA * DD + kA);
    float2 f10 = *(const float2*)(base + (size_t)(tA + 8) * DD + kA);
    float2 f01 = *(const float2*)(base + (size_t)tA * DD + kA + 8);
    float2 f11 = *(const float2*)(base + (size_t)(tA + 8) * DD + kA + 8);
    uint4 o;
    o.x = pack_h2(f00.x, f00.y);
    o.y = pack_h2(f10.x, f10.y);
    o.z = pack_h2(f01.x, f01.y);
    o.w = pack_h2(f11.x, f11.y);
    g_afrag[gidx] = o;
}

// ---------------- prep: W1 -> fp16 fragment-major (2 n8 per uint4) ----------------
__global__ void prep_bfrag_kernel(const float* __restrict__ W1) {
    int gidx = blockIdx.x * 256 + threadIdx.x;      // 32768
    int lane = gidx & 31;
    int k16 = (gidx >> 5) & 31;
    int n4 = gidx >> 10;
    int g = lane >> 2, tg = lane & 3;
    int k = k16 * 16 + 2 * tg;
    int ua = (2 * n4) * 8 + g;
    int ub = (2 * n4 + 1) * 8 + g;
    uint4 o;
    o.x = pack_h2(W1[(size_t)k * UU + ua],       W1[(size_t)(k + 1) * UU + ua]);
    o.y = pack_h2(W1[(size_t)(k + 8) * UU + ua], W1[(size_t)(k + 9) * UU + ua]);
    o.z = pack_h2(W1[(size_t)k * UU + ub],       W1[(size_t)(k + 1) * UU + ub]);
    o.w = pack_h2(W1[(size_t)(k + 8) * UU + ub], W1[(size_t)(k + 9) * UU + ub]);
    g_bfrag[gidx] = o;
}

// ---------------- comb[b][u] ----------------
__global__ void comb_kernel(const float* __restrict__ hidden,
                            const float* __restrict__ W2,
                            const float* __restrict__ W1b,
                            const float* __restrict__ W2b) {
    int b = blockIdx.x;
    int u = threadIdx.x;
    __shared__ float h[DD];
    h[u] = hidden[b * DD + u];
    __syncthreads();
    float acc = W1b[u] + W2b[u];
#pragma unroll 8
    for (int d = 0; d < DD; ++d)
        acc = fmaf(h[d], W2[d * UU + u], acc);
    g_comb[b * UU + u] = acc;
}

// ---------------- score GEMM: A via thread-private cp.async ring (no barriers) ----------------
// grid (2 nchunk, 16 ttile, 64 b), 512 threads = 16 warps (4 warpM x 4 warpN)
// A ring: 4 stages x 16KB (A0 block 8KB + A1 block 8KB), thread-private 16B slots.
#define RING_STAGE 16384
#define RING_BYTES 65536

__global__ void __launch_bounds__(512)
score_kernel(const float* __restrict__ Vw) {
    extern __shared__ char ring[];
    __shared__ float comb_s[256];
    __shared__ float v_s[256];
    __shared__ float srow[128];

    uint32_t ringb = smem_u32(ring);
    int tid = threadIdx.x;
    int wid = tid >> 5, lane = tid & 31;
    int warpM = wid & 3, warpN = wid >> 2;
    int g = lane >> 2, tg = lane & 3;

    int nchunk = blockIdx.x;
    int t0 = blockIdx.y << 7;
    int b = blockIdx.z;
    int u0 = nchunk << 8;

    if (tid < 256) {
        comb_s[tid] = g_comb[b * UU + u0 + tid];
        v_s[tid] = Vw[u0 + tid];
    }
    if (tid < 128) srow[tid] = 0.f;

    int tt0 = (t0 >> 4) + warpM * 2;
    const uint4* pA0 = g_afrag + (((size_t)(b * 128 + tt0) * 32) * 32 + lane);
    const uint4* pA1 = pA0 + 32 * 32;
    const uint4* pB  = g_bfrag + (((size_t)(nchunk * 16 + warpN * 4) * 32) * 32 + lane);

    // thread-private ring slots (lanes contiguous 16B -> conflict-free LDS.128)
    uint32_t slot = ringb + tid * 16;

    auto fill = [&](int c, int s) {
        uint32_t dst = slot + s * RING_STAGE;
        cpa16(dst, pA0 + c * 32);
        cpa16(dst + 8192, pA1 + c * 32);
        CP_COMMIT();
    };

    float acc[2][8][4];
#pragma unroll
    for (int i = 0; i < 2; ++i)
#pragma unroll
        for (int j = 0; j < 8; ++j)
#pragma unroll
            for (int q = 0; q < 4; ++q) acc[i][j][q] = 0.f;

    fill(0, 0);
    fill(1, 1);
    fill(2, 2);

    uint4 Bb[2][4];
#pragma unroll
    for (int j = 0; j < 4; ++j) Bb[0][j] = pB[j * 1024];

#pragma unroll 2
    for (int k16 = 0; k16 < 32; ++k16) {
        int cur = k16 & 1, nxt = cur ^ 1;
        // prefetch next A stage (distance 3) and next B (distance 1)
        if (k16 < 29) fill(k16 + 3, (k16 + 3) & 3);
        if (k16 < 31) {
            int off = (k16 + 1) * 32;
#pragma unroll
            for (int j = 0; j < 4; ++j) Bb[nxt][j] = pB[j * 1024 + off];
        }
        // wait for current A stage (per-thread, no barrier)
        if (k16 < 29)      { CP_WAIT(3); }
        else if (k16 == 29){ CP_WAIT(2); }
        else if (k16 == 30){ CP_WAIT(1); }
        else               { CP_WAIT(0); }

        uint32_t sbase = slot + (k16 & 3) * RING_STAGE;
        uint4 A0, A1;
        asm volatile("ld.shared.v4.u32 {%0,%1,%2,%3}, [%4];"
                     : "=r"(A0.x), "=r"(A0.y), "=r"(A0.z), "=r"(A0.w) : "r"(sbase));
        asm volatile("ld.shared.v4.u32 {%0,%1,%2,%3}, [%4];"
                     : "=r"(A1.x), "=r"(A1.y), "=r"(A1.z), "=r"(A1.w) : "r"(sbase + 8192));

#pragma unroll
        for (int n4 = 0; n4 < 4; ++n4) {
            uint4 B4 = Bb[cur][n4];
            mma_f16(acc[0][2 * n4],     A0, B4.x, B4.y);
            mma_f16(acc[0][2 * n4 + 1], A0, B4.z, B4.w);
            mma_f16(acc[1][2 * n4],     A1, B4.x, B4.y);
            mma_f16(acc[1][2 * n4 + 1], A1, B4.z, B4.w);
        }
    }

    __syncthreads();

    float s[4] = {0.f, 0.f, 0.f, 0.f};
#pragma unroll
    for (int nt = 0; nt < 8; ++nt) {
#pragma unroll
        for (int j = 0; j < 2; ++j) {
            int ul = warpN * 64 + nt * 8 + 2 * tg + j;
            float cb = comb_s[ul], vv = v_s[ul];
            s[0] = fmaf(vv, tanh_fast(acc[0][nt][j] + cb), s[0]);
            s[1] = fmaf(vv, tanh_fast(acc[0][nt][2 + j] + cb), s[1]);
            s[2] = fmaf(vv, tanh_fast(acc[1][nt][j] + cb), s[2]);
            s[3] = fmaf(vv, tanh_fast(acc[1][nt][2 + j] + cb), s[3]);
        }
    }
#pragma unroll
    for (int i = 0; i < 4; ++i) {
        s[i] += __shfl_xor_sync(0xffffffffu, s[i], 1);
        s[i] += __shfl_xor_sync(0xffffffffu, s[i], 2);
    }
    if (tg == 0) {
        int rbase = warpM * 32;
        atomicAdd(&srow[rbase + g], s[0]);
        atomicAdd(&srow[rbase + g + 8], s[1]);
        atomicAdd(&srow[rbase + 16 + g], s[2]);
        atomicAdd(&srow[rbase + 16 + g + 8], s[3]);
    }
    __syncthreads();
    if (tid < 128)
        g_spart[(size_t)nchunk * BB * TT + b * TT + t0 + tid] = srow[tid];
}

// ---------------- context: inline softmax stats + fp16-fragment reduction ----------------
__global__ void __launch_bounds__(256)
ctx_kernel(float* __restrict__ out) {
    int b = blockIdx.x;
    int kg = blockIdx.y;
    int tid = threadIdx.x;
    int wid = tid >> 5, lane = tid & 31;
    int g = lane >> 2, tg = lane & 3;
    int k16 = kg * 8 + wid;

    __shared__ float w[TT];
    __shared__ float red[256];

    float m = -INFINITY;
    for (int t = tid; t < TT; t += 256) {
        float sc = g_spart[b * TT + t] + g_spart[BB * TT + b * TT + t];
        w[t] = sc;
        m = fmaxf(m, sc);
    }
    red[tid] = m;
    __syncthreads();
    for (int s = 128; s > 0; s >>= 1) {
        if (tid < s) red[tid] = fmaxf(red[tid], red[tid + s]);
        __syncthreads();
    }
    float mx = red[0];
    __syncthreads();
    float sm = 0.f;
    for (int t = tid; t < TT; t += 256)
        sm += expf(w[t] - mx);
    red[tid] = sm;
    __syncthreads();
    for (int s = 128; s > 0; s >>= 1) {
        if (tid < s) red[tid] += red[tid + s];
        __syncthreads();
    }
    float inv = 1.0f / red[0];
    __syncthreads();
    for (int t = tid; t < TT; t += 256)
        w[t] = expf(w[t] - mx) * inv;
    __syncthreads();

    const uint4* pA = g_afrag + (((size_t)(b * 128) * 32 + k16) * 32 + lane);
    float a0 = 0.f, a1 = 0.f, a2 = 0.f, a3 = 0.f;
#pragma unroll 4
    for (int t16 = 0; t16 < 128; ++t16) {
        uint4 v = pA[(size_t)t16 * 1024];
        float wlo = w[t16 * 16 + g];
        float whi = w[t16 * 16 + 8 + g];
        float2 f;
        f = __half22float2(*(__half2*)&v.x);
        a0 = fmaf(wlo, f.x, a0); a1 = fmaf(wlo, f.y, a1);
        f = __half22float2(*(__half2*)&v.y);
        a0 = fmaf(whi, f.x, a0); a1 = fmaf(whi, f.y, a1);
        f = __half22float2(*(__half2*)&v.z);
        a2 = fmaf(wlo, f.x, a2); a3 = fmaf(wlo, f.y, a3);
        f = __half22float2(*(__half2*)&v.w);
        a2 = fmaf(whi, f.x, a2); a3 = fmaf(whi, f.y, a3);
    }
#pragma unroll
    for (int o = 4; o <= 16; o <<= 1) {
        a0 += __shfl_xor_sync(0xffffffffu, a0, o);
        a1 += __shfl_xor_sync(0xffffffffu, a1, o);
        a2 += __shfl_xor_sync(0xffffffffu, a2, o);
        a3 += __shfl_xor_sync(0xffffffffu, a3, o);
    }
    if (g == 0) {
        int d = k16 * 16 + 2 * tg;
        out[b * DD + d]     = a0;
        out[b * DD + d + 1] = a1;
        out[b * DD + d + 8] = a2;
        out[b * DD + d + 9] = a3;
    }
}

// ---------------- launch ----------------
extern "C" void kernel_launch(void* const* d_in, const int* in_sizes, int n_in,
                              void* d_out, int out_size) {
    const float* features = (const float*)d_in[0];
    const float* hidden   = (const float*)d_in[1];
    const float* W1_w     = (const float*)d_in[2];
    const float* W1_b     = (const float*)d_in[3];
    const float* W2_w     = (const float*)d_in[4];
    const float* W2_b     = (const float*)d_in[5];
    const float* V_w      = (const float*)d_in[6];
    // V_b: constant shift, softmax-invariant -> dropped
    float* out = (float*)d_out;

    cudaFuncSetAttribute(score_kernel, cudaFuncAttributeMaxDynamicSharedMemorySize, RING_BYTES);

    prep_afrag_kernel<<<BB * 128 * 32 * 32 / 256, 256>>>(features);
    prep_bfrag_kernel<<<32 * 32 * 32 / 256, 256>>>(W1_w);
    comb_kernel<<<BB, UU>>>(hidden, W2_w, W1_b, W2_b);

    dim3 sgrid(2, 16, BB);
    score_kernel<<<sgrid, 512, RING_BYTES>>>(V_w);

    dim3 cgrid(BB, 4);
    ctx_kernel<<<cgrid, 256>>>(out);
}

// round 15
// speedup vs baseline: 1.3106x; 1.0102x over previous
#include <cuda_runtime.h>
#include <cuda_fp16.h>
#include <math.h>
#include <stdint.h>

#define BB 64
#define TT 2048
#define DD 512
#define UU 512

// ---------------- device scratch ----------------
__device__ float g_comb[BB * UU];
__device__ float g_spart[2 * BB * TT];
__device__ float g_wts[BB * TT];
// A fragments: [b][t16 0..127][k16 0..31][lane 0..31] -> uint4 (a0,a1,a2,a3) fp16x2
__device__ uint4 g_afrag[BB * 128 * 32 * 32];
// B fragments (fp16, 2 n8 per uint4): [n4 0..31][k16 0..31][lane 0..31]
__device__ uint4 g_bfrag[32 * 32 * 32];

// ---------------- helpers ----------------
__device__ __forceinline__ uint32_t pack_h2(float x, float y) {
    __half2 h = __floats2half2_rn(x, y);
    return *(uint32_t*)&h;
}

__device__ __forceinline__ float tanh_fast(float x) {
    float y;
    asm("tanh.approx.f32 %0, %1;" : "=f"(y) : "f"(x));
    return y;
}

__device__ __forceinline__ void mma_f16(float* d, const uint4& a, uint32_t b0, uint32_t b1) {
    asm volatile(
        "mma.sync.aligned.m16n8k16.row.col.f32.f16.f16.f32 "
        "{%0,%1,%2,%3}, {%4,%5,%6,%7}, {%8,%9}, {%0,%1,%2,%3};"
        : "+f"(d[0]), "+f"(d[1]), "+f"(d[2]), "+f"(d[3])
        : "r"(a.x), "r"(a.y), "r"(a.z), "r"(a.w), "r"(b0), "r"(b1));
}

// ---------------- prep: features fp32 -> fp16 fragment-major (2 k16 per thread) ----------------
__global__ void prep_afrag_kernel(const float* __restrict__ feat) {
    int gidx = blockIdx.x * 256 + threadIdx.x;      // 4194304
    int lane = gidx & 31;
    int k16h = (gidx >> 5) & 15;
    int t16 = (gidx >> 9) & 127;
    int b = gidx >> 16;
    int g = lane >> 2, tg = lane & 3;
    int tA = t16 * 16 + g;
    const float* base = feat + ((size_t)b * TT + tA) * DD;
#pragma unroll
    for (int i = 0; i < 2; ++i) {
        int k16 = k16h * 2 + i;
        int kA = k16 * 16 + 2 * tg;
        float2 f00 = *(const float2*)(base + kA);
        float2 f10 = *(const float2*)(base + 8 * DD + kA);
        float2 f01 = *(const float2*)(base + kA + 8);
        float2 f11 = *(const float2*)(base + 8 * DD + kA + 8);
        uint4 o;
        o.x = pack_h2(f00.x, f00.y);
        o.y = pack_h2(f10.x, f10.y);
        o.z = pack_h2(f01.x, f01.y);
        o.w = pack_h2(f11.x, f11.y);
        g_afrag[(((size_t)(b * 128 + t16) * 32) + k16) * 32 + lane] = o;
    }
}

// ---------------- merged: comb (blocks 0..63) + prep_bfrag (blocks 64..127) ----------------
__global__ void __launch_bounds__(512)
comb_bfrag_kernel(const float* __restrict__ hidden,
                  const float* __restrict__ W2,
                  const float* __restrict__ W1b,
                  const float* __restrict__ W2b,
                  const float* __restrict__ W1) {
    int blk = blockIdx.x;
    int tid = threadIdx.x;
    if (blk < 64) {
        // comb[b][u]
        int b = blk;
        __shared__ float h[DD];
        h[tid] = hidden[b * DD + tid];
        __syncthreads();
        float acc = W1b[tid] + W2b[tid];
#pragma unroll 8
        for (int d = 0; d < DD; ++d)
            acc = fmaf(h[d], W2[d * UU + tid], acc);
        g_comb[b * UU + tid] = acc;
    } else {
        // prep_bfrag: gidx over 32768
        int gidx = (blk - 64) * 512 + tid;
        int lane = gidx & 31;
        int k16 = (gidx >> 5) & 31;
        int n4 = gidx >> 10;
        int g = lane >> 2, tg = lane & 3;
        int k = k16 * 16 + 2 * tg;
        int ua = (2 * n4) * 8 + g;
        int ub = (2 * n4 + 1) * 8 + g;
        uint4 o;
        o.x = pack_h2(W1[(size_t)k * UU + ua],       W1[(size_t)(k + 1) * UU + ua]);
        o.y = pack_h2(W1[(size_t)(k + 8) * UU + ua], W1[(size_t)(k + 9) * UU + ua]);
        o.z = pack_h2(W1[(size_t)k * UU + ub],       W1[(size_t)(k + 1) * UU + ub]);
        o.w = pack_h2(W1[(size_t)(k + 8) * UU + ub], W1[(size_t)(k + 9) * UU + ub]);
        g_bfrag[gidx] = o;
    }
}

// ---------------- score GEMM: R12 winner (byte-identical mainloop) ----------------
__global__ void __launch_bounds__(512)
score_kernel(const float* __restrict__ Vw) {
    __shared__ float comb_s[256];
    __shared__ float v_s[256];
    __shared__ float srow[128];

    int tid = threadIdx.x;
    int wid = tid >> 5, lane = tid & 31;
    int warpM = wid & 3, warpN = wid >> 2;
    int g = lane >> 2, tg = lane & 3;

    int nchunk = blockIdx.x;
    int t0 = blockIdx.y << 7;
    int b = blockIdx.z;
    int u0 = nchunk << 8;

    if (tid < 256) {
        comb_s[tid] = g_comb[b * UU + u0 + tid];
        v_s[tid] = Vw[u0 + tid];
    }
    if (tid < 128) srow[tid] = 0.f;

    int tt0 = (t0 >> 4) + warpM * 2;
    const uint4* pA0 = g_afrag + (((size_t)(b * 128 + tt0) * 32) * 32 + lane);
    const uint4* pA1 = pA0 + 32 * 32;
    const uint4* pB  = g_bfrag + (((size_t)(nchunk * 16 + warpN * 4) * 32) * 32 + lane);

    float acc[2][8][4];
#pragma unroll
    for (int i = 0; i < 2; ++i)
#pragma unroll
        for (int j = 0; j < 8; ++j)
#pragma unroll
            for (int q = 0; q < 4; ++q) acc[i][j][q] = 0.f;

    uint4 Ab[2][2], Bb[2][4];
    Ab[0][0] = pA0[0];
    Ab[0][1] = pA1[0];
#pragma unroll
    for (int j = 0; j < 4; ++j) Bb[0][j] = pB[j * 1024];

#pragma unroll 2
    for (int k16 = 0; k16 < 32; ++k16) {
        int cur = k16 & 1, nxt = cur ^ 1;
        if (k16 < 31) {
            int off = (k16 + 1) * 32;
            Ab[nxt][0] = pA0[off];
            Ab[nxt][1] = pA1[off];
#pragma unroll
            for (int j = 0; j < 4; ++j) Bb[nxt][j] = pB[j * 1024 + off];
        }
#pragma unroll
        for (int n4 = 0; n4 < 4; ++n4) {
            uint4 B4 = Bb[cur][n4];
            mma_f16(acc[0][2 * n4],     Ab[cur][0], B4.x, B4.y);
            mma_f16(acc[0][2 * n4 + 1], Ab[cur][0], B4.z, B4.w);
            mma_f16(acc[1][2 * n4],     Ab[cur][1], B4.x, B4.y);
            mma_f16(acc[1][2 * n4 + 1], Ab[cur][1], B4.z, B4.w);
        }
    }

    __syncthreads();

    float s[4] = {0.f, 0.f, 0.f, 0.f};
#pragma unroll
    for (int nt = 0; nt < 8; ++nt) {
#pragma unroll
        for (int j = 0; j < 2; ++j) {
            int ul = warpN * 64 + nt * 8 + 2 * tg + j;
            float cb = comb_s[ul], vv = v_s[ul];
            s[0] = fmaf(vv, tanh_fast(acc[0][nt][j] + cb), s[0]);
            s[1] = fmaf(vv, tanh_fast(acc[0][nt][2 + j] + cb), s[1]);
            s[2] = fmaf(vv, tanh_fast(acc[1][nt][j] + cb), s[2]);
            s[3] = fmaf(vv, tanh_fast(acc[1][nt][2 + j] + cb), s[3]);
        }
    }
#pragma unroll
    for (int i = 0; i < 4; ++i) {
        s[i] += __shfl_xor_sync(0xffffffffu, s[i], 1);
        s[i] += __shfl_xor_sync(0xffffffffu, s[i], 2);
    }
    if (tg == 0) {
        int rbase = warpM * 32;
        atomicAdd(&srow[rbase + g], s[0]);
        atomicAdd(&srow[rbase + g + 8], s[1]);
        atomicAdd(&srow[rbase + 16 + g], s[2]);
        atomicAdd(&srow[rbase + 16 + g + 8], s[3]);
    }
    __syncthreads();
    if (tid < 128)
        g_spart[(size_t)nchunk * BB * TT + b * TT + t0 + tid] = srow[tid];
}

// ---------------- softmax weights (once per b) ----------------
__global__ void __launch_bounds__(256)
wts_kernel() {
    int b = blockIdx.x;
    int tid = threadIdx.x;   // 256
    __shared__ float sc_s[TT];
    __shared__ float red[256];

    float m = -INFINITY;
    for (int t = tid; t < TT; t += 256) {
        float sc = g_spart[b * TT + t] + g_spart[BB * TT + b * TT + t];
        sc_s[t] = sc;
        m = fmaxf(m, sc);
    }
    red[tid] = m;
    __syncthreads();
    for (int s = 128; s > 0; s >>= 1) {
        if (tid < s) red[tid] = fmaxf(red[tid], red[tid + s]);
        __syncthreads();
    }
    float mx = red[0];
    __syncthreads();
    float sm = 0.f;
    for (int t = tid; t < TT; t += 256)
        sm += expf(sc_s[t] - mx);
    red[tid] = sm;
    __syncthreads();
    for (int s = 128; s > 0; s >>= 1) {
        if (tid < s) red[tid] += red[tid + s];
        __syncthreads();
    }
    float inv = 1.0f / red[0];
    for (int t = tid; t < TT; t += 256)
        g_wts[b * TT + t] = expf(sc_s[t] - mx) * inv;
}

// ---------------- context: weighted reduction over fp16 fragments ----------------
// grid (64 b, 4 kgroup), 256 threads = 8 warps; warp w -> k16 = kgroup*8 + w
__global__ void __launch_bounds__(256)
ctx_kernel(float* __restrict__ out) {
    int b = blockIdx.x;
    int kg = blockIdx.y;
    int tid = threadIdx.x;
    int wid = tid >> 5, lane = tid & 31;
    int g = lane >> 2, tg = lane & 3;
    int k16 = kg * 8 + wid;

    __shared__ float w[TT];
    for (int t = tid; t < TT; t += 256)
        w[t] = g_wts[b * TT + t];
    __syncthreads();

    const uint4* pA = g_afrag + (((size_t)(b * 128) * 32 + k16) * 32 + lane);
    float a0 = 0.f, a1 = 0.f, a2 = 0.f, a3 = 0.f;
#pragma unroll 4
    for (int t16 = 0; t16 < 128; ++t16) {
        uint4 v = pA[(size_t)t16 * 1024];
        float wlo = w[t16 * 16 + g];
        float whi = w[t16 * 16 + 8 + g];
        float2 f;
        f = __half22float2(*(__half2*)&v.x);
        a0 = fmaf(wlo, f.x, a0); a1 = fmaf(wlo, f.y, a1);
        f = __half22float2(*(__half2*)&v.y);
        a0 = fmaf(whi, f.x, a0); a1 = fmaf(whi, f.y, a1);
        f = __half22float2(*(__half2*)&v.z);
        a2 = fmaf(wlo, f.x, a2); a3 = fmaf(wlo, f.y, a3);
        f = __half22float2(*(__half2*)&v.w);
        a2 = fmaf(whi, f.x, a2); a3 = fmaf(whi, f.y, a3);
    }
#pragma unroll
    for (int o = 4; o <= 16; o <<= 1) {
        a0 += __shfl_xor_sync(0xffffffffu, a0, o);
        a1 += __shfl_xor_sync(0xffffffffu, a1, o);
        a2 += __shfl_xor_sync(0xffffffffu, a2, o);
        a3 += __shfl_xor_sync(0xffffffffu, a3, o);
    }
    if (g == 0) {
        int d = k16 * 16 + 2 * tg;
        out[b * DD + d]     = a0;
        out[b * DD + d + 1] = a1;
        out[b * DD + d + 8] = a2;
        out[b * DD + d + 9] = a3;
    }
}

// ---------------- launch ----------------
extern "C" void kernel_launch(void* const* d_in, const int* in_sizes, int n_in,
                              void* d_out, int out_size) {
    const float* features = (const float*)d_in[0];
    const float* hidden   = (const float*)d_in[1];
    const float* W1_w     = (const float*)d_in[2];
    const float* W1_b     = (const float*)d_in[3];
    const float* W2_w     = (const float*)d_in[4];
    const float* W2_b     = (const float*)d_in[5];
    const float* V_w      = (const float*)d_in[6];
    // V_b: constant shift, softmax-invariant -> dropped
    float* out = (float*)d_out;

    prep_afrag_kernel<<<BB * 128 * 16 * 32 / 256, 256>>>(features);
    comb_bfrag_kernel<<<128, 512>>>(hidden, W2_w, W1_b, W2_b, W1_w);

    dim3 sgrid(2, 16, BB);
    score_kernel<<<sgrid, 512>>>(V_w);

    wts_kernel<<<BB, 256>>>();

    dim3 cgrid(BB, 4);
    ctx_kernel<<<cgrid, 256>>>(out);
}